// round 1
// baseline (speedup 1.0000x reference)
#include <cuda_runtime.h>

// DockBoardAttention: B=65536 tiny attentions.
// Precompute (prep kernel):
//   W1[m][c] = 0.25 * sum_d Wq[d][m] * Wk[d][c]      (25x32, includes 1/sqrt(HD))
//   b1[c]    = 0.25 * sum_d bq[d]    * Wk[d][c]
//   W2[e][c] = sum_d Wo[e][d] * Wv[d][c]             (16x32)
//   b2[e]    = sum_d Wo[e][d] * bv[d] + bo[e]
// Per batch (warp):
//   QWk[n][c] = dock[n][:] @ W1 + b1                 (bk drops out of softmax)
//   logits[n][s] = sum_c QWk[n][c] * g[c][s]
//   attn = softmax over s (64)
//   AG[n][c] = sum_s attn[n][s] * g[c][s]
//   out[n][e] = sum_c W2[e][c] * AG[n][c] + b2[e]

#define NDOCK 3
#define DCELL 25
#define CCH   32
#define HW    64
#define HD    16
#define WPB   4     // warps per block

__device__ float g_W1[DCELL * CCH];
__device__ float g_b1[CCH];
__device__ float g_W2[HD * CCH];
__device__ float g_b2[HD];

__global__ void prep_kernel(const float* __restrict__ Wq, const float* __restrict__ bq,
                            const float* __restrict__ Wk,
                            const float* __restrict__ Wv, const float* __restrict__ bv,
                            const float* __restrict__ Wo, const float* __restrict__ bo) {
    int t = threadIdx.x;
    if (t < DCELL * CCH) {
        int m = t / CCH, c = t % CCH;
        float s = 0.f;
        #pragma unroll
        for (int d = 0; d < HD; d++) s += Wq[d * DCELL + m] * Wk[d * CCH + c];
        g_W1[t] = 0.25f * s;
    }
    if (t < CCH) {
        float s = 0.f;
        #pragma unroll
        for (int d = 0; d < HD; d++) s += bq[d] * Wk[d * CCH + t];
        g_b1[t] = 0.25f * s;
    }
    if (t < HD * CCH) {
        int e = t / CCH, c = t % CCH;
        float s = 0.f;
        #pragma unroll
        for (int d = 0; d < HD; d++) s += Wo[e * HD + d] * Wv[d * CCH + c];
        g_W2[t] = s;
    }
    if (t < HD) {
        float s = bo[t];
        #pragma unroll
        for (int d = 0; d < HD; d++) s += Wo[t * HD + d] * bv[d];
        g_b2[t] = s;
    }
}

__global__ __launch_bounds__(WPB * 32) void dock_attn_kernel(
    const float* __restrict__ dock, const float* __restrict__ grid,
    float* __restrict__ out, int nbatch)
{
    __shared__ float sW1[DCELL * 32];      // [m][c] pitch 32
    __shared__ float sb1[32];
    __shared__ float sW2[HD * 36];         // [e][c] pitch 36 (16B aligned rows)
    __shared__ float sb2[HD];
    __shared__ float sdock[WPB][3 * 28];   // 3 rows pitch 28 (float4-friendly)
    __shared__ float sqwk[WPB][3 * 32];
    __shared__ float str [WPB][32 * 36];   // transpose buffer, pitch 36
    __shared__ float sag [WPB][3 * 36];

    const int tid = threadIdx.x;
    const int w = tid >> 5, l = tid & 31;
    int b = (blockIdx.x << 2) + w;
    if (b >= nbatch) b = nbatch - 1;       // duplicate work, identical writes

    // ---- weights -> shared ----
    for (int i = tid; i < DCELL * 32; i += WPB * 32) sW1[i] = g_W1[i];
    for (int i = tid; i < HD * 32; i += WPB * 32)
        sW2[(i >> 5) * 36 + (i & 31)] = g_W2[i];
    if (tid < 32) sb1[tid] = g_b1[tid];
    if (tid < HD) sb2[tid] = g_b2[tid];

    // ---- g tile -> registers: lane owns s = 2l, 2l+1 for all 32 channels ----
    const float2* gp = reinterpret_cast<const float2*>(grid + (size_t)b * (CCH * HW)) + l;
    float2 G[32];
    #pragma unroll
    for (int c = 0; c < 32; c++) G[c] = __ldcs(gp + c * 32);

    // ---- dock -> shared (padded rows of 28) ----
    {
        const float* dp = dock + (size_t)b * (NDOCK * DCELL);
        float v0 = __ldcs(dp + l);
        float v1 = __ldcs(dp + 32 + l);
        int i0 = l, i1 = 32 + l;
        sdock[w][(i0 / 25) * 28 + (i0 % 25)] = v0;
        sdock[w][(i1 / 25) * 28 + (i1 % 25)] = v1;
        if (l < 11) {
            float v2 = __ldcs(dp + 64 + l);
            int i2 = 64 + l;
            sdock[w][(i2 / 25) * 28 + (i2 % 25)] = v2;
        }
    }
    __syncthreads();

    // ---- QWk[n][c=l] = dock[n][:] @ W1[:,l] + b1[l] ----
    float q0 = sb1[l], q1 = q0, q2 = q0;
    #pragma unroll
    for (int m4 = 0; m4 < 24; m4 += 4) {
        const float4 a0 = *(const float4*)&sdock[w][m4];
        const float4 a1 = *(const float4*)&sdock[w][28 + m4];
        const float4 a2 = *(const float4*)&sdock[w][56 + m4];
        float w0 = sW1[(m4 + 0) * 32 + l];
        float w1 = sW1[(m4 + 1) * 32 + l];
        float w2 = sW1[(m4 + 2) * 32 + l];
        float w3 = sW1[(m4 + 3) * 32 + l];
        q0 = fmaf(a0.x, w0, q0); q0 = fmaf(a0.y, w1, q0);
        q0 = fmaf(a0.z, w2, q0); q0 = fmaf(a0.w, w3, q0);
        q1 = fmaf(a1.x, w0, q1); q1 = fmaf(a1.y, w1, q1);
        q1 = fmaf(a1.z, w2, q1); q1 = fmaf(a1.w, w3, q1);
        q2 = fmaf(a2.x, w0, q2); q2 = fmaf(a2.y, w1, q2);
        q2 = fmaf(a2.z, w2, q2); q2 = fmaf(a2.w, w3, q2);
    }
    {
        float w0 = sW1[24 * 32 + l];
        q0 = fmaf(sdock[w][24], w0, q0);
        q1 = fmaf(sdock[w][28 + 24], w0, q1);
        q2 = fmaf(sdock[w][56 + 24], w0, q2);
    }
    sqwk[w][l] = q0; sqwk[w][32 + l] = q1; sqwk[w][64 + l] = q2;
    __syncwarp();

    // ---- per-n: logits -> softmax -> attn-weighted channel sums (AG) ----
    #pragma unroll
    for (int n = 0; n < 3; n++) {
        float ax = 0.f, ay = 0.f;
        #pragma unroll
        for (int c4 = 0; c4 < 32; c4 += 4) {
            const float4 qq = *(const float4*)&sqwk[w][n * 32 + c4];
            ax = fmaf(qq.x, G[c4 + 0].x, ax); ay = fmaf(qq.x, G[c4 + 0].y, ay);
            ax = fmaf(qq.y, G[c4 + 1].x, ax); ay = fmaf(qq.y, G[c4 + 1].y, ay);
            ax = fmaf(qq.z, G[c4 + 2].x, ax); ay = fmaf(qq.z, G[c4 + 2].y, ay);
            ax = fmaf(qq.w, G[c4 + 3].x, ax); ay = fmaf(qq.w, G[c4 + 3].y, ay);
        }
        // softmax over the 64 s values (2 per lane)
        float mx = fmaxf(ax, ay);
        #pragma unroll
        for (int o = 16; o > 0; o >>= 1)
            mx = fmaxf(mx, __shfl_xor_sync(0xffffffffu, mx, o));
        float ex = __expf(ax - mx), ey = __expf(ay - mx);
        float sm = ex + ey;
        #pragma unroll
        for (int o = 16; o > 0; o >>= 1)
            sm += __shfl_xor_sync(0xffffffffu, sm, o);
        float inv = __fdividef(1.f, sm);
        ex *= inv; ey *= inv;

        // per-lane partial AG over its 2 s values, store row (pitch 36, STS.128
        // conflict-free per 8-lane phase), then each lane sums a column.
        #pragma unroll
        for (int c4 = 0; c4 < 32; c4 += 4) {
            float4 p;
            p.x = fmaf(ex, G[c4 + 0].x, ey * G[c4 + 0].y);
            p.y = fmaf(ex, G[c4 + 1].x, ey * G[c4 + 1].y);
            p.z = fmaf(ex, G[c4 + 2].x, ey * G[c4 + 2].y);
            p.w = fmaf(ex, G[c4 + 3].x, ey * G[c4 + 3].y);
            *(float4*)&str[w][l * 36 + c4] = p;
        }
        __syncwarp();
        float s0 = 0.f, s1 = 0.f, s2 = 0.f, s3 = 0.f;
        #pragma unroll
        for (int i = 0; i < 32; i += 4) {
            s0 += str[w][(i + 0) * 36 + l];
            s1 += str[w][(i + 1) * 36 + l];
            s2 += str[w][(i + 2) * 36 + l];
            s3 += str[w][(i + 3) * 36 + l];
        }
        sag[w][n * 36 + l] = (s0 + s1) + (s2 + s3);
        __syncwarp();
    }

    // ---- out[n][e] = W2[e][:] . AG[n][:] + b2[e] ----
    // lane l -> output j1 = l (n = l>>4, e = l&15); lanes 0..15 also j2 = 32+l (n=2, e=l)
    {
        const int n1 = l >> 4, e1 = l & 15;
        float o1 = sb2[e1];
        float o2 = sb2[e1];                 // for lanes >=16 this result is unused
        const float* w2r = &sW2[e1 * 36];
        const float* ag1 = &sag[w][n1 * 36];
        const float* ag2 = &sag[w][2 * 36];
        #pragma unroll
        for (int c4 = 0; c4 < 32; c4 += 4) {
            const float4 wv = *(const float4*)(w2r + c4);
            const float4 a1 = *(const float4*)(ag1 + c4);
            const float4 a2 = *(const float4*)(ag2 + c4);
            o1 = fmaf(wv.x, a1.x, o1); o1 = fmaf(wv.y, a1.y, o1);
            o1 = fmaf(wv.z, a1.z, o1); o1 = fmaf(wv.w, a1.w, o1);
            o2 = fmaf(wv.x, a2.x, o2); o2 = fmaf(wv.y, a2.y, o2);
            o2 = fmaf(wv.z, a2.z, o2); o2 = fmaf(wv.w, a2.w, o2);
        }
        float* op = out + (size_t)b * (NDOCK * HD);
        op[l] = o1;
        if (l < 16) op[32 + l] = o2;
    }
}

extern "C" void kernel_launch(void* const* d_in, const int* in_sizes, int n_in,
                              void* d_out, int out_size) {
    const float* dock = (const float*)d_in[0];
    const float* grid = (const float*)d_in[1];
    const float* Wq   = (const float*)d_in[2];
    const float* bq   = (const float*)d_in[3];
    const float* Wk   = (const float*)d_in[4];
    // d_in[5] = bk: softmax-invariant, unused
    const float* Wv   = (const float*)d_in[6];
    const float* bv   = (const float*)d_in[7];
    const float* Wo   = (const float*)d_in[8];
    const float* bo   = (const float*)d_in[9];
    float* out = (float*)d_out;

    int nbatch = in_sizes[0] / (NDOCK * DCELL);

    prep_kernel<<<1, DCELL * CCH>>>(Wq, bq, Wk, Wv, bv, Wo, bo);
    int nblocks = (nbatch + WPB - 1) / WPB;
    dock_attn_kernel<<<nblocks, WPB * 32>>>(dock, grid, out, nbatch);
}

// round 6
// speedup vs baseline: 1.1129x; 1.1129x over previous
#include <cuda_runtime.h>

// DockBoardAttention: B=65536 tiny attentions.
// Precompute (prep kernel):
//   W1[m][c] = 0.25 * sum_d Wq[d][m] * Wk[d][c]      (25x32, includes 1/sqrt(HD))
//   b1[c]    = 0.25 * sum_d bq[d]    * Wk[d][c]
//   W2[e][c] = sum_d Wo[e][d] * Wv[d][c]             (16x32)
//   b2[e]    = sum_d Wo[e][d] * bv[d] + bo[e]
// Per batch (warp):
//   QWk[n][c] = dock[n][:] @ W1 + b1                 (bk drops out of softmax)
//   logits[n][s] = sum_c QWk[n][c] * g[c][s]
//   attn = softmax over s (64)
//   AG[n][c] = sum_s attn[n][s] * g[c][s]            (butterfly shuffle reduce)
//   out[n][e] = sum_c W2[e][c] * AG[n][c] + b2[e]

#define NDOCK 3
#define DCELL 25
#define CCH   32
#define HW    64
#define HD    16
#define WPB   4     // warps per block

__device__ float g_W1[DCELL * CCH];
__device__ float g_b1[CCH];
__device__ float g_W2[HD * CCH];
__device__ float g_b2[HD];

__global__ void prep_kernel(const float* __restrict__ Wq, const float* __restrict__ bq,
                            const float* __restrict__ Wk,
                            const float* __restrict__ Wv, const float* __restrict__ bv,
                            const float* __restrict__ Wo, const float* __restrict__ bo) {
    int t = threadIdx.x;
    if (t < DCELL * CCH) {
        int m = t / CCH, c = t % CCH;
        float s = 0.f;
        #pragma unroll
        for (int d = 0; d < HD; d++) s += Wq[d * DCELL + m] * Wk[d * CCH + c];
        g_W1[t] = 0.25f * s;
    }
    if (t < CCH) {
        float s = 0.f;
        #pragma unroll
        for (int d = 0; d < HD; d++) s += bq[d] * Wk[d * CCH + t];
        g_b1[t] = 0.25f * s;
    }
    if (t < HD * CCH) {
        int e = t / CCH, c = t % CCH;
        float s = 0.f;
        #pragma unroll
        for (int d = 0; d < HD; d++) s += Wo[e * HD + d] * Wv[d * CCH + c];
        g_W2[t] = s;
    }
    if (t < HD) {
        float s = bo[t];
        #pragma unroll
        for (int d = 0; d < HD; d++) s += Wo[t * HD + d] * bv[d];
        g_b2[t] = s;
    }
}

// Butterfly exchange-reduce stage: halves the owned-channel set per stage.
#define XSTAGE(o, h)                                                        \
    {                                                                       \
        const bool hi_ = (l & (o)) != 0;                                    \
        _Pragma("unroll")                                                   \
        for (int i_ = 0; i_ < (h); i_++) {                                  \
            float send_ = hi_ ? A[i_] : A[i_ + (h)];                        \
            float recv_ = __shfl_xor_sync(0xffffffffu, send_, (o));         \
            float keep_ = hi_ ? A[i_ + (h)] : A[i_];                        \
            A[i_] = keep_ + recv_;                                          \
        }                                                                   \
    }

__global__ __launch_bounds__(WPB * 32) void dock_attn_kernel(
    const float* __restrict__ dock, const float* __restrict__ grid,
    float* __restrict__ out, int nbatch)
{
    __shared__ float sW1[DCELL * 32];      // [m][c] pitch 32
    __shared__ float sb1[32];
    __shared__ float sW2[HD * 36];         // [e][c] pitch 36 (16B aligned rows)
    __shared__ float sb2[HD];
    __shared__ float sdock[WPB][3 * 28];   // 3 rows pitch 28 (float4-friendly)
    __shared__ float sqwk[WPB][3 * 32];
    __shared__ float sag [WPB][3 * 36];

    const int tid = threadIdx.x;
    const int w = tid >> 5, l = tid & 31;
    int b = (blockIdx.x << 2) + w;
    if (b >= nbatch) b = nbatch - 1;       // duplicate work, identical writes

    // ---- weights -> shared ----
    for (int i = tid; i < DCELL * 32; i += WPB * 32) sW1[i] = g_W1[i];
    for (int i = tid; i < HD * 32; i += WPB * 32)
        sW2[(i >> 5) * 36 + (i & 31)] = g_W2[i];
    if (tid < 32) sb1[tid] = g_b1[tid];
    if (tid < HD) sb2[tid] = g_b2[tid];

    // ---- g tile -> registers: lane owns s = 2l, 2l+1 for all 32 channels ----
    const float2* gp = reinterpret_cast<const float2*>(grid + (size_t)b * (CCH * HW)) + l;
    float2 G[32];
    #pragma unroll
    for (int c = 0; c < 32; c++) G[c] = __ldcs(gp + c * 32);

    // ---- dock -> shared (padded rows of 28) ----
    {
        const float* dp = dock + (size_t)b * (NDOCK * DCELL);
        float v0 = __ldcs(dp + l);
        float v1 = __ldcs(dp + 32 + l);
        int i0 = l, i1 = 32 + l;
        sdock[w][(i0 / 25) * 28 + (i0 % 25)] = v0;
        sdock[w][(i1 / 25) * 28 + (i1 % 25)] = v1;
        if (l < 11) {
            float v2 = __ldcs(dp + 64 + l);
            int i2 = 64 + l;
            sdock[w][(i2 / 25) * 28 + (i2 % 25)] = v2;
        }
    }
    __syncthreads();

    // ---- QWk[n][c=l] = dock[n][:] @ W1[:,l] + b1[l] ----
    float q0 = sb1[l], q1 = q0, q2 = q0;
    #pragma unroll
    for (int m4 = 0; m4 < 24; m4 += 4) {
        const float4 a0 = *(const float4*)&sdock[w][m4];
        const float4 a1 = *(const float4*)&sdock[w][28 + m4];
        const float4 a2 = *(const float4*)&sdock[w][56 + m4];
        float w0 = sW1[(m4 + 0) * 32 + l];
        float w1 = sW1[(m4 + 1) * 32 + l];
        float w2 = sW1[(m4 + 2) * 32 + l];
        float w3 = sW1[(m4 + 3) * 32 + l];
        q0 = fmaf(a0.x, w0, q0); q0 = fmaf(a0.y, w1, q0);
        q0 = fmaf(a0.z, w2, q0); q0 = fmaf(a0.w, w3, q0);
        q1 = fmaf(a1.x, w0, q1); q1 = fmaf(a1.y, w1, q1);
        q1 = fmaf(a1.z, w2, q1); q1 = fmaf(a1.w, w3, q1);
        q2 = fmaf(a2.x, w0, q2); q2 = fmaf(a2.y, w1, q2);
        q2 = fmaf(a2.z, w2, q2); q2 = fmaf(a2.w, w3, q2);
    }
    {
        float w0 = sW1[24 * 32 + l];
        q0 = fmaf(sdock[w][24], w0, q0);
        q1 = fmaf(sdock[w][28 + 24], w0, q1);
        q2 = fmaf(sdock[w][56 + 24], w0, q2);
    }
    sqwk[w][l] = q0; sqwk[w][32 + l] = q1; sqwk[w][64 + l] = q2;
    __syncwarp();

    // ---- per-n: logits -> softmax -> attn-weighted channel sums (AG) ----
    #pragma unroll
    for (int n = 0; n < 3; n++) {
        float ax = 0.f, ay = 0.f;
        #pragma unroll
        for (int c4 = 0; c4 < 32; c4 += 4) {
            const float4 qq = *(const float4*)&sqwk[w][n * 32 + c4];
            ax = fmaf(qq.x, G[c4 + 0].x, ax); ay = fmaf(qq.x, G[c4 + 0].y, ay);
            ax = fmaf(qq.y, G[c4 + 1].x, ax); ay = fmaf(qq.y, G[c4 + 1].y, ay);
            ax = fmaf(qq.z, G[c4 + 2].x, ax); ay = fmaf(qq.z, G[c4 + 2].y, ay);
            ax = fmaf(qq.w, G[c4 + 3].x, ax); ay = fmaf(qq.w, G[c4 + 3].y, ay);
        }
        // softmax over the 64 s values (2 per lane)
        float mx = fmaxf(ax, ay);
        #pragma unroll
        for (int o = 16; o > 0; o >>= 1)
            mx = fmaxf(mx, __shfl_xor_sync(0xffffffffu, mx, o));
        float ex = __expf(ax - mx), ey = __expf(ay - mx);
        float sm = ex + ey;
        #pragma unroll
        for (int o = 16; o > 0; o >>= 1)
            sm += __shfl_xor_sync(0xffffffffu, sm, o);
        float inv = __fdividef(1.f, sm);
        ex *= inv; ey *= inv;

        // Butterfly exchange-reduce over lanes: after 5 xor stages lane l holds
        // AG[n][c=l] = sum over all 64 s of attn*g. Stage 1 (o=16) is fused with
        // the per-lane partial computation to cap register liveness at A[16].
        float A[16];
        {
            const bool hi_ = (l & 16) != 0;
            #pragma unroll
            for (int i = 0; i < 16; i++) {
                float Pl = fmaf(ex, G[i].x,      ey * G[i].y);
                float Ph = fmaf(ex, G[i + 16].x, ey * G[i + 16].y);
                float send_ = hi_ ? Pl : Ph;
                float recv_ = __shfl_xor_sync(0xffffffffu, send_, 16);
                float keep_ = hi_ ? Ph : Pl;
                A[i] = keep_ + recv_;
            }
        }
        XSTAGE(8, 8)
        XSTAGE(4, 4)
        XSTAGE(2, 2)
        XSTAGE(1, 1)
        sag[w][n * 36 + l] = A[0];
    }
    __syncwarp();

    // ---- out[n][e] = W2[e][:] . AG[n][:] + b2[e] ----
    // lane l -> output j1 = l (n = l>>4, e = l&15); lanes 0..15 also j2 = 32+l (n=2, e=l)
    {
        const int n1 = l >> 4, e1 = l & 15;
        float o1 = sb2[e1];
        float o2 = sb2[e1];                 // for lanes >=16 this result is unused
        const float* w2r = &sW2[e1 * 36];
        const float* ag1 = &sag[w][n1 * 36];
        const float* ag2 = &sag[w][2 * 36];
        #pragma unroll
        for (int c4 = 0; c4 < 32; c4 += 4) {
            const float4 wv = *(const float4*)(w2r + c4);
            const float4 a1 = *(const float4*)(ag1 + c4);
            const float4 a2 = *(const float4*)(ag2 + c4);
            o1 = fmaf(wv.x, a1.x, o1); o1 = fmaf(wv.y, a1.y, o1);
            o1 = fmaf(wv.z, a1.z, o1); o1 = fmaf(wv.w, a1.w, o1);
            o2 = fmaf(wv.x, a2.x, o2); o2 = fmaf(wv.y, a2.y, o2);
            o2 = fmaf(wv.z, a2.z, o2); o2 = fmaf(wv.w, a2.w, o2);
        }
        float* op = out + (size_t)b * (NDOCK * HD);
        op[l] = o1;
        if (l < 16) op[32 + l] = o2;
    }
}

extern "C" void kernel_launch(void* const* d_in, const int* in_sizes, int n_in,
                              void* d_out, int out_size) {
    const float* dock = (const float*)d_in[0];
    const float* grid = (const float*)d_in[1];
    const float* Wq   = (const float*)d_in[2];
    const float* bq   = (const float*)d_in[3];
    const float* Wk   = (const float*)d_in[4];
    // d_in[5] = bk: softmax-invariant, unused
    const float* Wv   = (const float*)d_in[6];
    const float* bv   = (const float*)d_in[7];
    const float* Wo   = (const float*)d_in[8];
    const float* bo   = (const float*)d_in[9];
    float* out = (float*)d_out;

    int nbatch = in_sizes[0] / (NDOCK * DCELL);

    prep_kernel<<<1, DCELL * CCH>>>(Wq, bq, Wk, Wv, bv, Wo, bo);
    int nblocks = (nbatch + WPB - 1) / WPB;
    dock_attn_kernel<<<nblocks, WPB * 32>>>(dock, grid, out, nbatch);
}